// round 5
// baseline (speedup 1.0000x reference)
#include <cuda_runtime.h>
#include <cuda_bf16.h>
#include <cstddef>

#define BATCH 8
#define CDIM  64
#define HDIM  256
#define WDIM  256
#define WH    65536
#define CWH   (CDIM*WH)

// -------------------- scratch --------------------
__device__ float g_q [BATCH * CWH];   // dq(x)      (depthwise-only)
__device__ float g_k [BATCH * CWH];   // k = full DSC(x)
__device__ float g_v [BATCH * CWH];   // dv(x)+dv(avg) (depthwise-only, 2*db)
__device__ float g_qm[BATCH * CWH];   // dq(mask)
__device__ float g_part1[BATCH * 64 * 4096];
__device__ float g_part2[BATCH * 64 * 4096];
__device__ float g_R1[BATCH * 4096];
__device__ float g_R2[BATCH * 4096];
__device__ float g_cs_part[BATCH * 64 * 64];  // colsum_k partials per chunk
__device__ float g_Mp[BATCH * 4096];          // (A1+A2) @ Pv
__device__ float g_cvec[BATCH * 64];          // (A1+A2) @ (2*pbv)

__device__ __forceinline__ float* out_buf(int id) {
    return id == 0 ? g_q : id == 1 ? g_k : id == 2 ? g_v : g_qm;
}

// -------------------- f32x2 helpers --------------------
typedef unsigned long long u64t;
__device__ __forceinline__ u64t pk2(float lo, float hi) {
    u64t r; asm("mov.b64 %0, {%1,%2};" : "=l"(r) : "f"(lo), "f"(hi)); return r;
}
__device__ __forceinline__ void unpk(u64t a, float& x, float& y) {
    asm("mov.b64 {%0,%1}, %2;" : "=f"(x), "=f"(y) : "l"(a));
}
__device__ __forceinline__ u64t fma2(u64t a, u64t b, u64t c) {
    u64t d; asm("fma.rn.f32x2 %0, %1, %2, %3;" : "=l"(d) : "l"(a), "l"(b), "l"(c)); return d;
}
__device__ __forceinline__ u64t add2(u64t a, u64t b) {
    u64t d; asm("add.rn.f32x2 %0, %1, %2;" : "=l"(d) : "l"(a), "l"(b)); return d;
}

// -------------------- cp.async helpers --------------------
__device__ __forceinline__ void cp16(void* s, const void* g) {
    unsigned sa = (unsigned)__cvta_generic_to_shared(s);
    asm volatile("cp.async.cg.shared.global [%0], [%1], 16;\n" :: "r"(sa), "l"(g));
}
__device__ __forceinline__ void cp_commit() { asm volatile("cp.async.commit_group;\n"); }
template<int N> __device__ __forceinline__ void cp_wait() {
    asm volatile("cp.async.wait_group %0;\n" :: "n"(N));
}

// -------------------- depthwise 3x3 standalone --------------------
template <int NSET, bool ACCUM>
__global__ __launch_bounds__(256)
void dw_kernel(const float* __restrict__ in,
               const float* __restrict__ wA, const float* __restrict__ bA, float* __restrict__ oA,
               const float* __restrict__ wB, const float* __restrict__ bB, float* __restrict__ oB)
{
    __shared__ float xs[10][264];
    const int tid = threadIdx.x;
    const int c  = blockIdx.y;
    const int b  = blockIdx.z;
    const int y0 = blockIdx.x * 8;

    const float* inp = in + ((size_t)b * CDIM + c) * WH;

#pragma unroll
    for (int r = 0; r < 10; r++) {
        int y = y0 - 1 + r;
        xs[r][1 + tid] = (y >= 0 && y < HDIM) ? inp[y * WDIM + tid] : 0.0f;
    }
    if (tid < 10) { xs[tid][0] = 0.0f; xs[tid][257] = 0.0f; }

    const float* ws[2] = { wA, wB };
    const float* bs[2] = { bA, bB };
    float*       os[2] = { oA, oB };
    float w[NSET][9], bias[NSET];
#pragma unroll
    for (int s = 0; s < NSET; s++) {
#pragma unroll
        for (int i = 0; i < 9; i++) w[s][i] = ws[s][c * 9 + i];
        bias[s] = bs[s][c];
    }
    __syncthreads();

    float r0a = xs[0][tid], r0b = xs[0][tid + 1], r0c = xs[0][tid + 2];
    float r1a = xs[1][tid], r1b = xs[1][tid + 1], r1c = xs[1][tid + 2];
    float r2a = xs[2][tid], r2b = xs[2][tid + 1], r2c = xs[2][tid + 2];

    const size_t obase = ((size_t)b * CDIM + c) * WH + (size_t)y0 * WDIM + tid;

#pragma unroll
    for (int r = 0; r < 8; r++) {
#pragma unroll
        for (int s = 0; s < NSET; s++) {
            float acc = bias[s];
            acc += w[s][0] * r0a + w[s][1] * r0b + w[s][2] * r0c;
            acc += w[s][3] * r1a + w[s][4] * r1b + w[s][5] * r1c;
            acc += w[s][6] * r2a + w[s][7] * r2b + w[s][8] * r2c;
            size_t gi = obase + (size_t)r * WDIM;
            if (ACCUM) os[s][gi] += acc;
            else       os[s][gi]  = acc;
        }
        if (r < 7) {
            r0a = r1a; r0b = r1b; r0c = r1c;
            r1a = r2a; r1b = r2b; r1c = r2c;
            r2a = xs[r + 3][tid]; r2b = xs[r + 3][tid + 1]; r2c = xs[r + 3][tid + 2];
        }
    }
}

// -------------------- fused depthwise-separable conv (k only) ------------
struct DscP {
    const float* dw;
    const float* db;
    const float* pw;
    const float* pb;
    int out_id;
};

#define DSC_SMEM_FLOATS (20736 + 16384 + 8192 + 576 + 64 + 64)

__global__ __launch_bounds__(512, 1)
void dsc_kernel(const float* __restrict__ in, DscP P)
{
    extern __shared__ float sm[];
    float* xs    = sm;
    float* dwout = xs + 20736;
    float* pwq   = dwout + 16384;
    float* fsm   = pwq + 8192;
    float* dbsm  = fsm + 576;
    float* pbsm  = dbsm + 64;

    const int tid = threadIdx.x;
    const int b   = blockIdx.z;
    const int ty0 = blockIdx.y * 16;
    const int tx0 = blockIdx.x * 16;

    const float* inb = in + (size_t)b * CWH;
    for (int idx = tid; idx < 20736; idx += 512) {
        int c = idx / 324, r = idx % 324;
        int yy = r / 18 - 1 + ty0;
        int xx = r % 18 - 1 + tx0;
        float v = 0.0f;
        if (yy >= 0 && yy < HDIM && xx >= 0 && xx < WDIM)
            v = inb[c * WH + yy * WDIM + xx];
        xs[idx] = v;
    }

    const int px2  = tid & 127;
    const int c0   = tid >> 7;
    const int drow = (2 * px2) >> 4;
    const int dcol = (2 * px2) & 15;
    const int pp = tid & 63;
    const int og = tid >> 6;

    for (int i = tid; i < 576; i += 512) fsm[i] = P.dw[i];
    for (int idx = tid; idx < 2048; idx += 512) {
        int o = idx >> 5, cc = idx & 31;
        float w0 = P.pw[o * 64 + 2 * cc];
        float w1 = P.pw[o * 64 + 2 * cc + 1];
        ((float4*)pwq)[idx] = make_float4(w0, w0, w1, w1);
    }
    if (tid < 64) { dbsm[tid] = P.db[tid]; pbsm[tid] = P.pb[tid]; }
    __syncthreads();

    for (int c = c0; c < 64; c += 4) {
        const float* base = xs + c * 324 + drow * 18 + dcol;
        float r[3][4];
#pragma unroll
        for (int dy = 0; dy < 3; dy++) {
            float2 a  = *(const float2*)(base + dy * 18);
            float2 b2 = *(const float2*)(base + dy * 18 + 2);
            r[dy][0] = a.x; r[dy][1] = a.y; r[dy][2] = b2.x; r[dy][3] = b2.y;
        }
        const float* w = fsm + c * 9;
        float s0 = dbsm[c], s1 = s0;
#pragma unroll
        for (int dy = 0; dy < 3; dy++) {
            s0 += w[3*dy] * r[dy][0] + w[3*dy+1] * r[dy][1] + w[3*dy+2] * r[dy][2];
            s1 += w[3*dy] * r[dy][1] + w[3*dy+1] * r[dy][2] + w[3*dy+2] * r[dy][3];
        }
        *(float2*)&dwout[c * 256 + 2 * px2] = make_float2(s0, s1);
    }
    __syncthreads();

    u64t acc[8][2];
#pragma unroll
    for (int i = 0; i < 8; i++) {
        float pbv = pbsm[og * 8 + i];
        acc[i][0] = pk2(pbv, pbv);
        acc[i][1] = acc[i][0];
    }
    for (int cc = 0; cc < 32; cc++) {
        int c2 = 2 * cc;
        u64t dA0 = *(const u64t*)&dwout[c2 * 256 + 2 * pp];
        u64t dA1 = *(const u64t*)&dwout[c2 * 256 + 128 + 2 * pp];
        u64t dB0 = *(const u64t*)&dwout[(c2 + 1) * 256 + 2 * pp];
        u64t dB1 = *(const u64t*)&dwout[(c2 + 1) * 256 + 128 + 2 * pp];
#pragma unroll
        for (int i = 0; i < 8; i++) {
            ulonglong2 w2 = *(const ulonglong2*)&pwq[((og * 8 + i) * 32 + cc) * 4];
            acc[i][0] = fma2(w2.x, dA0, acc[i][0]);
            acc[i][1] = fma2(w2.x, dA1, acc[i][1]);
            acc[i][0] = fma2(w2.y, dB0, acc[i][0]);
            acc[i][1] = fma2(w2.y, dB1, acc[i][1]);
        }
    }

    float* outp = out_buf(P.out_id) + (size_t)b * CWH;
    const int q0 = 2 * pp;
    const int gy0 = ty0 + (q0 >> 4), gx0 = tx0 + (q0 & 15);
    const size_t base0 = (size_t)gy0 * WDIM + gx0;
#pragma unroll
    for (int i = 0; i < 8; i++) {
        int o = og * 8 + i;
        size_t gi0 = (size_t)o * WH + base0;
        size_t gi1 = gi0 + 8 * WDIM;
        *(u64t*)&outp[gi0] = acc[i][0];
        *(u64t*)&outp[gi1] = acc[i][1];
    }
}

// -------------------- QK + in-flight colsum_k --------------------
#define QSTR 36
#define KSTR 68

__global__ __launch_bounds__(256)
void qk_kernel()
{
    const int b = blockIdx.y;
    const int chunk = blockIdx.x;
    const int p0 = chunk * 1024;
    const int tid = threadIdx.x;
    const int ti = tid >> 4, tj = tid & 15;
    const int i0 = ti * 4, j0 = tj * 4;

    __shared__ __align__(16) float q1s[2][64 * QSTR];
    __shared__ __align__(16) float q2s[2][64 * QSTR];
    __shared__ __align__(16) float ks [2][32 * KSTR];

    const float* qb  = g_q  + (size_t)b * CWH;
    const float* qmb = g_qm + (size_t)b * CWH;
    const float* kb  = g_k  + (size_t)b * CWH;

    auto prefetch = [&](int kt, int s) {
        const int pp2 = p0 + kt * 32;
        for (int e = tid; e < 512; e += 256) {
            int i = e >> 3, u4 = (e & 7) * 4;
            cp16(&q1s[s][i * QSTR + u4], qb  + (size_t)i * WH + pp2 + u4);
            cp16(&q2s[s][i * QSTR + u4], qmb + (size_t)i * WH + pp2 + u4);
        }
        for (int e = tid; e < 512; e += 256) {
            int u = e >> 4, j4 = (e & 15) * 4;
            cp16(&ks[s][u * KSTR + j4], kb + (size_t)(pp2 + u) * 64 + j4);
        }
        cp_commit();
    };

    u64t acc1[4][2] = {};
    u64t acc2[4][2] = {};
    float cs_acc = 0.0f;

    prefetch(0, 0);
    prefetch(1, 1);

    for (int kt = 0; kt < 32; kt++) {
        if (kt == 31) cp_wait<0>(); else cp_wait<1>();
        __syncthreads();
        const int cur = kt & 1;
#pragma unroll 2
        for (int u = 0; u < 32; u++) {
            ulonglong2 bv = *(const ulonglong2*)&ks[cur][u * KSTR + j0];
#pragma unroll
            for (int r = 0; r < 4; r++) {
                float av1 = q1s[cur][(i0 + r) * QSTR + u];
                u64t a1d = pk2(av1, av1);
                acc1[r][0] = fma2(a1d, bv.x, acc1[r][0]);
                acc1[r][1] = fma2(a1d, bv.y, acc1[r][1]);
                float av2 = q2s[cur][(i0 + r) * QSTR + u];
                u64t a2d = pk2(av2, av2);
                acc2[r][0] = fma2(a2d, bv.x, acc2[r][0]);
                acc2[r][1] = fma2(a2d, bv.y, acc2[r][1]);
            }
        }
        if (tid < 64) {
#pragma unroll 8
            for (int u = 0; u < 32; u++) cs_acc += ks[cur][u * KSTR + tid];
        }
        __syncthreads();
        if (kt + 2 < 32) prefetch(kt + 2, cur);
    }

    float* P1 = g_part1 + ((size_t)b * 64 + chunk) * 4096;
    float* P2 = g_part2 + ((size_t)b * 64 + chunk) * 4096;
#pragma unroll
    for (int r = 0; r < 4; r++) {
        float a, bb, c, d;
        unpk(acc1[r][0], a, bb); unpk(acc1[r][1], c, d);
        *(float4*)&P1[(i0 + r) * 64 + j0] = make_float4(a, bb, c, d);
        unpk(acc2[r][0], a, bb); unpk(acc2[r][1], c, d);
        *(float4*)&P2[(i0 + r) * 64 + j0] = make_float4(a, bb, c, d);
    }
    if (tid < 64) g_cs_part[((size_t)b * 64 + chunk) * 64 + tid] = cs_acc;
}

// -------------------- parallel partial reduce --------------------
__global__ __launch_bounds__(512)
void reduce_kernel()
{
    const int b = blockIdx.y;
    const int e = blockIdx.x * 512 + threadIdx.x;
    const float* P1 = g_part1 + (size_t)b * 64 * 4096;
    const float* P2 = g_part2 + (size_t)b * 64 * 4096;
    float s1 = 0.0f, s2 = 0.0f;
#pragma unroll 8
    for (int ch = 0; ch < 64; ch++) {
        s1 += P1[(size_t)ch * 4096 + e];
        s2 += P2[(size_t)ch * 4096 + e];
    }
    g_R1[(size_t)b * 4096 + e] = s1 * (1.0f / 256.0f);
    g_R2[(size_t)b * 4096 + e] = s2 * (1.0f / 256.0f);
}

// -------------------- tiny: Pq-apply + softmax x2 + fold Pv --------------------
#define TINY_SMEM_FLOATS (4 * 4096 + 256 + 64 + 64)

__global__ __launch_bounds__(256)
void tiny_kernel(const float* __restrict__ Pq, const float* __restrict__ pbq,
                 const float* __restrict__ Pv, const float* __restrict__ pbv)
{
    extern __shared__ float ts[];
    float* W   = ts;            // 4096 (Pq, later Pv)
    float* R   = W + 4096;      // 4096
    float* L   = R + 4096;      // 4096
    float* Msm = L + 4096;      // 4096
    float* red = Msm + 4096;    // 256
    float* cs  = red + 256;     // 64
    float* pbs = cs + 64;       // 64

    const int b = blockIdx.x;
    const int tid = threadIdx.x;

    if (tid < 64) {
        float s = 0.0f;
        for (int ch = 0; ch < 64; ch++)
            s += g_cs_part[((size_t)b * 64 + ch) * 64 + tid];
        cs[tid] = s * (1.0f / 256.0f);
        pbs[tid] = pbq[tid];
    }
    for (int e = tid; e < 4096; e += 256) W[e] = Pq[e];
    __syncthreads();

    for (int m = 0; m < 2; m++) {
        const float* Rg = (m == 0 ? g_R1 : g_R2) + (size_t)b * 4096;
        for (int e = tid; e < 4096; e += 256) R[e] = Rg[e];
        __syncthreads();
        for (int e = tid; e < 4096; e += 256) {
            int i = e >> 6, j = e & 63;
            float s = pbs[i] * cs[j];
#pragma unroll 8
            for (int a = 0; a < 64; a++) s += W[i * 64 + a] * R[a * 64 + j];
            L[e] = s;
        }
        __syncthreads();

        float lmax = -1e30f;
        for (int e = tid; e < 4096; e += 256) lmax = fmaxf(lmax, L[e]);
        red[tid] = lmax; __syncthreads();
        for (int s = 128; s; s >>= 1) {
            if (tid < s) red[tid] = fmaxf(red[tid], red[tid + s]);
            __syncthreads();
        }
        float mx = red[0]; __syncthreads();

        float lsum = 0.0f;
        for (int e = tid; e < 4096; e += 256) {
            float ev = __expf(L[e] - mx);
            L[e] = ev; lsum += ev;
        }
        red[tid] = lsum; __syncthreads();
        for (int s = 128; s; s >>= 1) {
            if (tid < s) red[tid] += red[tid + s];
            __syncthreads();
        }
        float inv = 1.0f / red[0]; __syncthreads();

        for (int e = tid; e < 4096; e += 256) {
            float v = L[e] * inv;
            if (m == 0) Msm[e] = v; else Msm[e] += v;
        }
        __syncthreads();
    }

    // fold Pv and pbv into M
    for (int e = tid; e < 4096; e += 256) W[e] = Pv[e];
    if (tid < 64) pbs[tid] = pbv[tid];
    __syncthreads();

    for (int e = tid; e < 4096; e += 256) {
        int i = e >> 6, o = e & 63;
        float s = 0.0f;
#pragma unroll 8
        for (int j = 0; j < 64; j++) s += Msm[i * 64 + j] * W[j * 64 + o];
        g_Mp[(size_t)b * 4096 + e] = s;
    }
    if (tid < 64) {
        float s = 0.0f;
        for (int j = 0; j < 64; j++) s += Msm[tid * 64 + j] * pbs[j];
        g_cvec[b * 64 + tid] = 2.0f * s;
    }
}

// -------------------- out = Mp @ dv_sum + cvec + x --------------------
#define OUT_SMEM_FLOATS (8192 + 2 * 8192 + 64)

__global__ __launch_bounds__(512)
void out_kernel(const float* __restrict__ x, float* __restrict__ out)
{
    extern __shared__ float osm[];
    float* mq = osm;          // 8192: 64 x 32 float4 (m,m,m',m')
    float* vt = osm + 8192;   // 2 x 64 x 128
    float* cv = vt + 2 * 8192;// 64

    const int b  = blockIdx.y;
    const int p0 = blockIdx.x * 512;
    const int tid = threadIdx.x;
    const int pp = tid & 63, og = tid >> 6;

    for (int idx = tid; idx < 2048; idx += 512) {
        int o = idx >> 5, cc = idx & 31;
        float m0 = g_Mp[(size_t)b * 4096 + o * 64 + 2 * cc];
        float m1 = g_Mp[(size_t)b * 4096 + o * 64 + 2 * cc + 1];
        ((float4*)mq)[idx] = make_float4(m0, m0, m1, m1);
    }
    if (tid < 64) cv[tid] = g_cvec[b * 64 + tid];

    const float* vb = g_v + (size_t)b * CWH + p0;

    auto prefetch = [&](int s, int buf) {
        const float* src = vb + s * 128;
        float* dst = vt + buf * 8192;
        for (int e = tid; e < 2048; e += 512) {
            int c = e >> 5, q4 = (e & 31) * 4;
            cp16(&dst[c * 128 + q4], src + (size_t)c * WH + q4);
        }
        cp_commit();
    };

    prefetch(0, 0);
    prefetch(1, 1);

    const float* xb = x + (size_t)b * CWH + p0 + 2 * pp;
    float* ob = out + (size_t)b * CWH + p0 + 2 * pp;

    for (int s = 0; s < 4; s++) {
        if (s == 3) cp_wait<0>(); else cp_wait<1>();
        __syncthreads();
        const float* cvt = vt + (s & 1) * 8192;

        u64t xr[8];
#pragma unroll
        for (int i = 0; i < 8; i++) {
            int o = og * 8 + i;
            xr[i] = *(const u64t*)(xb + (size_t)o * WH + s * 128);
        }

        u64t acc[8];
#pragma unroll
        for (int i = 0; i < 8; i++) {
            float c0 = cv[og * 8 + i];
            acc[i] = pk2(c0, c0);
        }
#pragma unroll 4
        for (int cc = 0; cc < 32; cc++) {
            u64t d0 = *(const u64t*)&cvt[(2 * cc) * 128 + 2 * pp];
            u64t d1 = *(const u64t*)&cvt[(2 * cc + 1) * 128 + 2 * pp];
#pragma unroll
            for (int i = 0; i < 8; i++) {
                ulonglong2 w2 = *(const ulonglong2*)&mq[((og * 8 + i) * 32 + cc) * 4];
                acc[i] = fma2(w2.x, d0, acc[i]);
                acc[i] = fma2(w2.y, d1, acc[i]);
            }
        }

#pragma unroll
        for (int i = 0; i < 8; i++) {
            int o = og * 8 + i;
            *(u64t*)(ob + (size_t)o * WH + s * 128) = add2(acc[i], xr[i]);
        }

        __syncthreads();
        if (s + 2 < 4) prefetch(s + 2, s & 1);
    }
}

// -------------------- launch --------------------
extern "C" void kernel_launch(void* const* d_in, const int* in_sizes, int n_in,
                              void* d_out, int out_size)
{
    const float* x    = (const float*)d_in[0];
    const float* mask = (const float*)d_in[1];
    const float* avg  = (const float*)d_in[2];
    const float* dwq = (const float*)d_in[3];
    const float* dbq = (const float*)d_in[4];
    const float* pwq = (const float*)d_in[5];
    const float* pbq = (const float*)d_in[6];
    DscP kP = { (const float*)d_in[7],  (const float*)d_in[8],
                (const float*)d_in[9],  (const float*)d_in[10], 1 };
    const float* dwv = (const float*)d_in[11];
    const float* dbv = (const float*)d_in[12];
    const float* pwv = (const float*)d_in[13];
    const float* pbv = (const float*)d_in[14];
    float* out = (float*)d_out;

    const size_t dsc_smem = DSC_SMEM_FLOATS * sizeof(float);
    cudaFuncSetAttribute(dsc_kernel, cudaFuncAttributeMaxDynamicSharedMemorySize, (int)dsc_smem);
    const size_t out_smem = OUT_SMEM_FLOATS * sizeof(float);
    cudaFuncSetAttribute(out_kernel, cudaFuncAttributeMaxDynamicSharedMemorySize, (int)out_smem);
    const size_t tiny_smem = TINY_SMEM_FLOATS * sizeof(float);
    cudaFuncSetAttribute(tiny_kernel, cudaFuncAttributeMaxDynamicSharedMemorySize, (int)tiny_smem);

    dim3 dwGrid(HDIM / 8, CDIM, BATCH);
    // x -> dq(x), dv(x)  (depthwise only)
    dw_kernel<2, false><<<dwGrid, 256>>>(x, dwq, dbq, g_q, dwv, dbv, g_v);
    // mask -> dq(mask)
    dw_kernel<1, false><<<dwGrid, 256>>>(mask, dwq, dbq, g_qm, dwq, dbq, g_qm);
    // avg -> dv(avg) accumulated (dv_sum carries 2*db_v)
    dw_kernel<1, true><<<dwGrid, 256>>>(avg, dwv, dbv, g_v, dwv, dbv, g_v);

    // x -> k (full DSC, only pointwise that cannot be factored out)
    dsc_kernel<<<dim3(WDIM / 16, HDIM / 16, BATCH), 512, dsc_smem>>>(x, kP);

    qk_kernel<<<dim3(64, BATCH), 256>>>();
    reduce_kernel<<<dim3(8, BATCH), 512>>>();
    tiny_kernel<<<BATCH, 256, tiny_smem>>>(pwq, pbq, pwv, pbv);
    out_kernel<<<dim3(WH / 512, BATCH), 512, out_smem>>>(x, out);
}

// round 6
// speedup vs baseline: 2.4075x; 2.4075x over previous
#include <cuda_runtime.h>
#include <cuda_bf16.h>
#include <cstddef>

#define BATCH 8
#define CDIM  64
#define HDIM  256
#define WDIM  256
#define WH    65536
#define CWH   (CDIM*WH)

// -------------------- scratch --------------------
__device__ float g_q [BATCH * CWH];
__device__ float g_k [BATCH * CWH];
__device__ float g_v [BATCH * CWH];
__device__ float g_qm[BATCH * CWH];
__device__ float g_part1[BATCH * 64 * 4096];
__device__ float g_part2[BATCH * 64 * 4096];
__device__ float g_R1[BATCH * 4096];
__device__ float g_R2[BATCH * 4096];
__device__ float g_M[BATCH * 4096];

__device__ __forceinline__ float* out_buf(int id) {
    return id == 0 ? g_q : id == 1 ? g_k : id == 2 ? g_v : g_qm;
}

// -------------------- f32x2 helpers --------------------
typedef unsigned long long u64t;
__device__ __forceinline__ u64t pk2(float lo, float hi) {
    u64t r; asm("mov.b64 %0, {%1,%2};" : "=l"(r) : "f"(lo), "f"(hi)); return r;
}
__device__ __forceinline__ void unpk(u64t a, float& x, float& y) {
    asm("mov.b64 {%0,%1}, %2;" : "=f"(x), "=f"(y) : "l"(a));
}
__device__ __forceinline__ u64t fma2(u64t a, u64t b, u64t c) {
    u64t d; asm("fma.rn.f32x2 %0, %1, %2, %3;" : "=l"(d) : "l"(a), "l"(b), "l"(c)); return d;
}
__device__ __forceinline__ u64t add2(u64t a, u64t b) {
    u64t d; asm("add.rn.f32x2 %0, %1, %2;" : "=l"(d) : "l"(a), "l"(b)); return d;
}

// -------------------- cp.async helpers --------------------
__device__ __forceinline__ void cp16(void* s, const void* g) {
    unsigned sa = (unsigned)__cvta_generic_to_shared(s);
    asm volatile("cp.async.cg.shared.global [%0], [%1], 16;\n" :: "r"(sa), "l"(g));
}
__device__ __forceinline__ void cp_commit() { asm volatile("cp.async.commit_group;\n"); }
template<int N> __device__ __forceinline__ void cp_wait() {
    asm volatile("cp.async.wait_group %0;\n" :: "n"(N));
}

// -------------------- fused DSC, 8x16 tile, 2 blocks/SM --------------------
struct DscP {
    const float* dw;
    const float* db;
    const float* pw;   // (64,64) [o][c]
    const float* pb;
    int out_id;
};

// smem floats: xs 64*180 + dwout 64*128 + pwq 8192 + fsm 576 + dbsm 64 + pbsm 64
#define DSC_SMEM_FLOATS (11520 + 8192 + 8192 + 576 + 64 + 64)

template <int NPROJ, bool ACCUM>
__global__ __launch_bounds__(256, 2)
void dsc_kernel(const float* __restrict__ in, DscP p0, DscP p1, DscP p2)
{
    extern __shared__ float sm[];
    float* xs    = sm;                 // 64 x 10 x 18
    float* dwout = xs + 11520;         // 64 x 128
    float* pwq   = dwout + 8192;       // 64 x 32 float4 (w,w,w',w')
    float* fsm   = pwq + 8192;         // 576
    float* dbsm  = fsm + 576;          // 64
    float* pbsm  = dbsm + 64;          // 64

    const int tid = threadIdx.x;
    const int b   = blockIdx.z;
    const int ty0 = blockIdx.y * 8;
    const int tx0 = blockIdx.x * 16;

    // tile load with halo: 64 ch x 10 rows x 18 cols
    const float* inb = in + (size_t)b * CWH;
    for (int idx = tid; idx < 11520; idx += 256) {
        int c = idx / 180, r = idx % 180;
        int yy = r / 18 - 1 + ty0;
        int xx = r % 18 - 1 + tx0;
        float v = 0.0f;
        if (yy >= 0 && yy < HDIM && xx >= 0 && xx < WDIM)
            v = inb[c * WH + yy * WDIM + xx];
        xs[idx] = v;
    }

    DscP ps[3] = {p0, p1, p2};
    // depthwise: pair p = tid&63 (2 adjacent px), channel group tid>>6 step 4
    const int dp   = tid & 63;
    const int cg   = tid >> 6;           // 0..3
    const int drow = (2 * dp) >> 4;
    const int dcol = (2 * dp) & 15;
    // pointwise: 8 outputs x 2 pixel-pairs per thread
    const int pp0 = tid & 31;            // pairs pp0 and pp0+32
    const int og  = tid >> 5;            // 0..7

#pragma unroll
    for (int ph = 0; ph < NPROJ; ph++) {
        DscP P = ps[ph];
        __syncthreads();   // prev phase done with dwout/pwq (and tile load done)
        for (int i = tid; i < 576; i += 256) fsm[i] = P.dw[i];
        for (int idx = tid; idx < 2048; idx += 256) {
            int o = idx >> 5, cc = idx & 31;
            float w0 = P.pw[o * 64 + 2 * cc];
            float w1 = P.pw[o * 64 + 2 * cc + 1];
            ((float4*)pwq)[idx] = make_float4(w0, w0, w1, w1);
        }
        if (tid < 64) { dbsm[tid] = P.db[tid]; pbsm[tid] = P.pb[tid]; }
        __syncthreads();

        // depthwise 3x3 + bias, 2 px per thread, 16 channels per thread
        for (int c = cg; c < 64; c += 4) {
            const float* base = xs + c * 180 + drow * 18 + dcol;
            float r[3][4];
#pragma unroll
            for (int dy = 0; dy < 3; dy++) {
                float2 a  = *(const float2*)(base + dy * 18);
                float2 b2 = *(const float2*)(base + dy * 18 + 2);
                r[dy][0] = a.x; r[dy][1] = a.y; r[dy][2] = b2.x; r[dy][3] = b2.y;
            }
            const float* w = fsm + c * 9;
            float s0 = dbsm[c], s1 = s0;
#pragma unroll
            for (int dy = 0; dy < 3; dy++) {
                s0 += w[3*dy] * r[dy][0] + w[3*dy+1] * r[dy][1] + w[3*dy+2] * r[dy][2];
                s1 += w[3*dy] * r[dy][1] + w[3*dy+1] * r[dy][2] + w[3*dy+2] * r[dy][3];
            }
            *(float2*)&dwout[c * 128 + 2 * dp] = make_float2(s0, s1);
        }
        __syncthreads();

        // pointwise 64x64 FFMA2: 8 outputs x 2 pixel-pairs
        u64t acc[8][2];
#pragma unroll
        for (int i = 0; i < 8; i++) {
            float pbv = pbsm[og * 8 + i];
            acc[i][0] = pk2(pbv, pbv);
            acc[i][1] = acc[i][0];
        }
        for (int cc = 0; cc < 32; cc++) {
            int c2 = 2 * cc;
            u64t dA0 = *(const u64t*)&dwout[c2 * 128 + 2 * pp0];
            u64t dA1 = *(const u64t*)&dwout[c2 * 128 + 64 + 2 * pp0];
            u64t dB0 = *(const u64t*)&dwout[(c2 + 1) * 128 + 2 * pp0];
            u64t dB1 = *(const u64t*)&dwout[(c2 + 1) * 128 + 64 + 2 * pp0];
#pragma unroll
            for (int i = 0; i < 8; i++) {
                ulonglong2 w2 = *(const ulonglong2*)&pwq[((og * 8 + i) * 32 + cc) * 4];
                acc[i][0] = fma2(w2.x, dA0, acc[i][0]);
                acc[i][1] = fma2(w2.x, dA1, acc[i][1]);
                acc[i][0] = fma2(w2.y, dB0, acc[i][0]);
                acc[i][1] = fma2(w2.y, dB1, acc[i][1]);
            }
        }

        // store: pairs at pixels (2pp0, 2pp0+1) and (+64 px = +4 rows)
        float* outp = out_buf(P.out_id) + (size_t)b * CWH;
        const int q0 = 2 * pp0;
        const int gy0 = ty0 + (q0 >> 4), gx0 = tx0 + (q0 & 15);
        const size_t base0 = (size_t)gy0 * WDIM + gx0;
#pragma unroll
        for (int i = 0; i < 8; i++) {
            int o = og * 8 + i;
            size_t gi0 = (size_t)o * WH + base0;
            size_t gi1 = gi0 + 4 * WDIM;
            if (ACCUM) {
                u64t x0 = *(const u64t*)&outp[gi0];
                u64t x1 = *(const u64t*)&outp[gi1];
                *(u64t*)&outp[gi0] = add2(acc[i][0], x0);
                *(u64t*)&outp[gi1] = add2(acc[i][1], x1);
            } else {
                *(u64t*)&outp[gi0] = acc[i][0];
                *(u64t*)&outp[gi1] = acc[i][1];
            }
        }
    }
}

// -------------------- QK (R4, verbatim) --------------------
#define QSTR 36
#define KSTR 68

__global__ __launch_bounds__(256)
void qk_kernel()
{
    const int b = blockIdx.y;
    const int chunk = blockIdx.x;
    const int p0 = chunk * 1024;
    const int tid = threadIdx.x;
    const int ti = tid >> 4, tj = tid & 15;
    const int i0 = ti * 4, j0 = tj * 4;

    __shared__ __align__(16) float q1s[2][64 * QSTR];
    __shared__ __align__(16) float q2s[2][64 * QSTR];
    __shared__ __align__(16) float ks [2][32 * KSTR];

    const float* qb  = g_q  + (size_t)b * CWH;
    const float* qmb = g_qm + (size_t)b * CWH;
    const float* kb  = g_k  + (size_t)b * CWH;

    auto prefetch = [&](int kt, int s) {
        const int pp2 = p0 + kt * 32;
        for (int e = tid; e < 512; e += 256) {
            int i = e >> 3, u4 = (e & 7) * 4;
            cp16(&q1s[s][i * QSTR + u4], qb  + (size_t)i * WH + pp2 + u4);
            cp16(&q2s[s][i * QSTR + u4], qmb + (size_t)i * WH + pp2 + u4);
        }
        for (int e = tid; e < 512; e += 256) {
            int u = e >> 4, j4 = (e & 15) * 4;
            cp16(&ks[s][u * KSTR + j4], kb + (size_t)(pp2 + u) * 64 + j4);
        }
        cp_commit();
    };

    u64t acc1[4][2] = {};
    u64t acc2[4][2] = {};

    prefetch(0, 0);
    prefetch(1, 1);

    for (int kt = 0; kt < 32; kt++) {
        if (kt == 31) cp_wait<0>(); else cp_wait<1>();
        __syncthreads();
        const int cur = kt & 1;
#pragma unroll 2
        for (int u = 0; u < 32; u++) {
            ulonglong2 bv = *(const ulonglong2*)&ks[cur][u * KSTR + j0];
#pragma unroll
            for (int r = 0; r < 4; r++) {
                float av1 = q1s[cur][(i0 + r) * QSTR + u];
                u64t a1d = pk2(av1, av1);
                acc1[r][0] = fma2(a1d, bv.x, acc1[r][0]);
                acc1[r][1] = fma2(a1d, bv.y, acc1[r][1]);
                float av2 = q2s[cur][(i0 + r) * QSTR + u];
                u64t a2d = pk2(av2, av2);
                acc2[r][0] = fma2(a2d, bv.x, acc2[r][0]);
                acc2[r][1] = fma2(a2d, bv.y, acc2[r][1]);
            }
        }
        __syncthreads();
        if (kt + 2 < 32) prefetch(kt + 2, cur);
    }

    float* P1 = g_part1 + ((size_t)b * 64 + chunk) * 4096;
    float* P2 = g_part2 + ((size_t)b * 64 + chunk) * 4096;
#pragma unroll
    for (int r = 0; r < 4; r++) {
        float a, bb, c, d;
        unpk(acc1[r][0], a, bb); unpk(acc1[r][1], c, d);
        *(float4*)&P1[(i0 + r) * 64 + j0] = make_float4(a, bb, c, d);
        unpk(acc2[r][0], a, bb); unpk(acc2[r][1], c, d);
        *(float4*)&P2[(i0 + r) * 64 + j0] = make_float4(a, bb, c, d);
    }
}

// -------------------- parallel partial reduce --------------------
__global__ __launch_bounds__(512)
void reduce_kernel()
{
    const int b = blockIdx.y;
    const int e = blockIdx.x * 512 + threadIdx.x;
    const float* P1 = g_part1 + (size_t)b * 64 * 4096;
    const float* P2 = g_part2 + (size_t)b * 64 * 4096;
    float s1 = 0.0f, s2 = 0.0f;
#pragma unroll 8
    for (int ch = 0; ch < 64; ch++) {
        s1 += P1[(size_t)ch * 4096 + e];
        s2 += P2[(size_t)ch * 4096 + e];
    }
    g_R1[(size_t)b * 4096 + e] = s1 * (1.0f / 256.0f);
    g_R2[(size_t)b * 4096 + e] = s2 * (1.0f / 256.0f);
}

// -------------------- softmax(flat 4096) x2 + M = A1+A2 --------------------
__global__ __launch_bounds__(256)
void softmax_kernel()
{
    __shared__ float buf[4096];
    __shared__ float red[256];
    const int b = blockIdx.x;
    const int tid = threadIdx.x;

    for (int m = 0; m < 2; m++) {
        const float* R = (m == 0 ? g_R1 : g_R2) + (size_t)b * 4096;
        __syncthreads();
        float lmax = -1e30f;
        for (int e = tid; e < 4096; e += 256) {
            float s = R[e];
            buf[e] = s;
            lmax = fmaxf(lmax, s);
        }
        red[tid] = lmax; __syncthreads();
        for (int s = 128; s; s >>= 1) {
            if (tid < s) red[tid] = fmaxf(red[tid], red[tid + s]);
            __syncthreads();
        }
        float mx = red[0];
        __syncthreads();

        float lsum = 0.0f;
        for (int e = tid; e < 4096; e += 256) {
            float ev = __expf(buf[e] - mx);
            buf[e] = ev;
            lsum += ev;
        }
        red[tid] = lsum; __syncthreads();
        for (int s = 128; s; s >>= 1) {
            if (tid < s) red[tid] += red[tid + s];
            __syncthreads();
        }
        float inv = 1.0f / red[0];

        for (int e = tid; e < 4096; e += 256) {
            float val = buf[e] * inv;
            float* mp = g_M + (size_t)b * 4096 + e;
            if (m == 0) *mp = val;
            else        *mp += val;
        }
    }
}

// -------------------- out = M @ v_sum + x, cp.async-staged (R4, verbatim) ------
#define OUT_SMEM_FLOATS (8192 + 2 * 8192)

__global__ __launch_bounds__(512)
void out_kernel(const float* __restrict__ x, float* __restrict__ out)
{
    extern __shared__ float osm[];
    float* mq = osm;          // 8192: 64 x 32 float4 (m,m,m',m')
    float* vt = osm + 8192;   // 2 x 64 x 128

    const int b  = blockIdx.y;
    const int p0 = blockIdx.x * 512;
    const int tid = threadIdx.x;
    const int pp = tid & 63, og = tid >> 6;

    for (int idx = tid; idx < 2048; idx += 512) {
        int o = idx >> 5, cc = idx & 31;
        float m0 = g_M[(size_t)b * 4096 + o * 64 + 2 * cc];
        float m1 = g_M[(size_t)b * 4096 + o * 64 + 2 * cc + 1];
        ((float4*)mq)[idx] = make_float4(m0, m0, m1, m1);
    }

    const float* vb = g_v + (size_t)b * CWH + p0;

    auto prefetch = [&](int s, int buf) {
        const float* src = vb + s * 128;
        float* dst = vt + buf * 8192;
        for (int e = tid; e < 2048; e += 512) {
            int c = e >> 5, q4 = (e & 31) * 4;
            cp16(&dst[c * 128 + q4], src + (size_t)c * WH + q4);
        }
        cp_commit();
    };

    prefetch(0, 0);
    prefetch(1, 1);

    const float* xb = x + (size_t)b * CWH + p0 + 2 * pp;
    float* ob = out + (size_t)b * CWH + p0 + 2 * pp;

    for (int s = 0; s < 4; s++) {
        if (s == 3) cp_wait<0>(); else cp_wait<1>();
        __syncthreads();
        const float* cvt = vt + (s & 1) * 8192;

        u64t xr[8];
#pragma unroll
        for (int i = 0; i < 8; i++) {
            int o = og * 8 + i;
            xr[i] = *(const u64t*)(xb + (size_t)o * WH + s * 128);
        }

        u64t acc[8] = {};
#pragma unroll 4
        for (int cc = 0; cc < 32; cc++) {
            u64t d0 = *(const u64t*)&cvt[(2 * cc) * 128 + 2 * pp];
            u64t d1 = *(const u64t*)&cvt[(2 * cc + 1) * 128 + 2 * pp];
#pragma unroll
            for (int i = 0; i < 8; i++) {
                ulonglong2 w2 = *(const ulonglong2*)&mq[((og * 8 + i) * 32 + cc) * 4];
                acc[i] = fma2(w2.x, d0, acc[i]);
                acc[i] = fma2(w2.y, d1, acc[i]);
            }
        }

#pragma unroll
        for (int i = 0; i < 8; i++) {
            int o = og * 8 + i;
            *(u64t*)(ob + (size_t)o * WH + s * 128) = add2(acc[i], xr[i]);
        }

        __syncthreads();
        if (s + 2 < 4) prefetch(s + 2, s & 1);
    }
}

// -------------------- launch --------------------
extern "C" void kernel_launch(void* const* d_in, const int* in_sizes, int n_in,
                              void* d_out, int out_size)
{
    const float* x    = (const float*)d_in[0];
    const float* mask = (const float*)d_in[1];
    const float* avg  = (const float*)d_in[2];
    DscP q = { (const float*)d_in[3],  (const float*)d_in[4],
               (const float*)d_in[5],  (const float*)d_in[6],  0 };
    DscP k = { (const float*)d_in[7],  (const float*)d_in[8],
               (const float*)d_in[9],  (const float*)d_in[10], 1 };
    DscP v = { (const float*)d_in[11], (const float*)d_in[12],
               (const float*)d_in[13], (const float*)d_in[14], 2 };
    DscP qm = q; qm.out_id = 3;
    float* out = (float*)d_out;

    const size_t dsc_smem = DSC_SMEM_FLOATS * sizeof(float);
    cudaFuncSetAttribute(dsc_kernel<3, false>, cudaFuncAttributeMaxDynamicSharedMemorySize, (int)dsc_smem);
    cudaFuncSetAttribute(dsc_kernel<1, false>, cudaFuncAttributeMaxDynamicSharedMemorySize, (int)dsc_smem);
    cudaFuncSetAttribute(dsc_kernel<1, true>,  cudaFuncAttributeMaxDynamicSharedMemorySize, (int)dsc_smem);
    const size_t out_smem = OUT_SMEM_FLOATS * sizeof(float);
    cudaFuncSetAttribute(out_kernel, cudaFuncAttributeMaxDynamicSharedMemorySize, (int)out_smem);

    dim3 dscGrid(WDIM / 16, HDIM / 8, BATCH);   // 16 x 32 x 8 = 4096 blocks

    dsc_kernel<3, false><<<dscGrid, 256, dsc_smem>>>(x, q, k, v);
    dsc_kernel<1, false><<<dscGrid, 256, dsc_smem>>>(mask, qm, qm, qm);
    dsc_kernel<1, true><<<dscGrid, 256, dsc_smem>>>(avg, v, v, v);

    qk_kernel<<<dim3(64, BATCH), 256>>>();
    reduce_kernel<<<dim3(8, BATCH), 512>>>();
    softmax_kernel<<<BATCH, 256>>>();
    out_kernel<<<dim3(WH / 512, BATCH), 512, out_smem>>>(x, out);
}